// round 5
// baseline (speedup 1.0000x reference)
#include <cuda_runtime.h>
#include <cuda_bf16.h>

#define CLAMP_MIN 1e-12f
#define CLAMP_MAX 1e12f

// Pre-normalized centers scratch (C <= 256, D = 256)
__device__ float g_cnorm[256 * 256];

// Prep: zero the output and write normalized centers (one warp per center row).
__global__ void prep_kernel(const float* __restrict__ centers, float* __restrict__ out, int C) {
    if (blockIdx.x == 0 && threadIdx.x == 0) out[0] = 0.0f;

    const int warp = (blockIdx.x * blockDim.x + threadIdx.x) >> 5;
    const int lane = threadIdx.x & 31;
    if (warp >= C) return;

    const float4* __restrict__ cr = reinterpret_cast<const float4*>(centers) + (size_t)warp * 64;
    float4 b0 = cr[lane];
    float4 b1 = cr[32 + lane];

    float s = 0.0f;
    s = fmaf(b0.x, b0.x, s); s = fmaf(b0.y, b0.y, s);
    s = fmaf(b0.z, b0.z, s); s = fmaf(b0.w, b0.w, s);
    s = fmaf(b1.x, b1.x, s); s = fmaf(b1.y, b1.y, s);
    s = fmaf(b1.z, b1.z, s); s = fmaf(b1.w, b1.w, s);

    #pragma unroll
    for (int off = 16; off > 0; off >>= 1)
        s += __shfl_xor_sync(0xFFFFFFFFu, s, off);

    const float inv = rsqrtf(fmaxf(s, 1e-24f));
    b0.x *= inv; b0.y *= inv; b0.z *= inv; b0.w *= inv;
    b1.x *= inv; b1.y *= inv; b1.z *= inv; b1.w *= inv;

    float4* __restrict__ dst = reinterpret_cast<float4*>(g_cnorm) + (size_t)warp * 64;
    dst[lane]      = b0;
    dst[32 + lane] = b1;
}

// Main: 8 lanes per row, 4 rows per warp-iteration.
// Front-batched 8x LDG.128 of ref_emb per lane (MLP 8), parallel 8-lane
// group reductions (5 shuffles per 4 rows).
__global__ __launch_bounds__(512)
void inner_cos_kernel(const float* __restrict__ ref_emb,
                      const int*   __restrict__ ref_label,
                      float* __restrict__ out,
                      int N, float inv_n) {
    const int lane = threadIdx.x & 31;
    const int wid  = threadIdx.x >> 5;
    const int warps_per_block = blockDim.x >> 5;
    const int gwarp = blockIdx.x * warps_per_block + wid;
    const int total_warps = gridDim.x * warps_per_block;

    const int sub = lane & 7;   // chunk within row
    const int grp = lane >> 3;  // row within warp-iteration

    __shared__ float ssum[16];

    float acc = 0.0f;  // meaningful on lanes 0, 8, 16, 24

    const int Nq = N & ~3;
    for (int r = gwarp * 4; r + 3 < Nq + 1; r += total_warps * 4) {
        const int row = r + grp;
        const int lab = __ldg(&ref_label[row]);

        const float4* __restrict__ xr = reinterpret_cast<const float4*>(ref_emb) + (size_t)row * 64 + sub;
        const float4* __restrict__ cr = reinterpret_cast<const float4*>(g_cnorm) + (size_t)lab * 64 + sub;

        // Front-batch all 8 emb loads: 8 independent LDG.128 in flight.
        float4 a0 = __ldcs(xr +  0);
        float4 a1 = __ldcs(xr +  8);
        float4 a2 = __ldcs(xr + 16);
        float4 a3 = __ldcs(xr + 24);
        float4 a4 = __ldcs(xr + 32);
        float4 a5 = __ldcs(xr + 40);
        float4 a6 = __ldcs(xr + 48);
        float4 a7 = __ldcs(xr + 56);

        float dot0 = 0.f, dot1 = 0.f, nx0 = 0.f, nx1 = 0.f;

        // Centers are L1-resident; fetch in pairs while emb loads drain.
        {
            float4 b0 = __ldg(cr + 0), b1 = __ldg(cr + 8);
            dot0 = fmaf(a0.x,b0.x,dot0); dot0 = fmaf(a0.y,b0.y,dot0);
            dot0 = fmaf(a0.z,b0.z,dot0); dot0 = fmaf(a0.w,b0.w,dot0);
            dot1 = fmaf(a1.x,b1.x,dot1); dot1 = fmaf(a1.y,b1.y,dot1);
            dot1 = fmaf(a1.z,b1.z,dot1); dot1 = fmaf(a1.w,b1.w,dot1);
            nx0  = fmaf(a0.x,a0.x,nx0);  nx0  = fmaf(a0.y,a0.y,nx0);
            nx0  = fmaf(a0.z,a0.z,nx0);  nx0  = fmaf(a0.w,a0.w,nx0);
            nx1  = fmaf(a1.x,a1.x,nx1);  nx1  = fmaf(a1.y,a1.y,nx1);
            nx1  = fmaf(a1.z,a1.z,nx1);  nx1  = fmaf(a1.w,a1.w,nx1);
        }
        {
            float4 b0 = __ldg(cr + 16), b1 = __ldg(cr + 24);
            dot0 = fmaf(a2.x,b0.x,dot0); dot0 = fmaf(a2.y,b0.y,dot0);
            dot0 = fmaf(a2.z,b0.z,dot0); dot0 = fmaf(a2.w,b0.w,dot0);
            dot1 = fmaf(a3.x,b1.x,dot1); dot1 = fmaf(a3.y,b1.y,dot1);
            dot1 = fmaf(a3.z,b1.z,dot1); dot1 = fmaf(a3.w,b1.w,dot1);
            nx0  = fmaf(a2.x,a2.x,nx0);  nx0  = fmaf(a2.y,a2.y,nx0);
            nx0  = fmaf(a2.z,a2.z,nx0);  nx0  = fmaf(a2.w,a2.w,nx0);
            nx1  = fmaf(a3.x,a3.x,nx1);  nx1  = fmaf(a3.y,a3.y,nx1);
            nx1  = fmaf(a3.z,a3.z,nx1);  nx1  = fmaf(a3.w,a3.w,nx1);
        }
        {
            float4 b0 = __ldg(cr + 32), b1 = __ldg(cr + 40);
            dot0 = fmaf(a4.x,b0.x,dot0); dot0 = fmaf(a4.y,b0.y,dot0);
            dot0 = fmaf(a4.z,b0.z,dot0); dot0 = fmaf(a4.w,b0.w,dot0);
            dot1 = fmaf(a5.x,b1.x,dot1); dot1 = fmaf(a5.y,b1.y,dot1);
            dot1 = fmaf(a5.z,b1.z,dot1); dot1 = fmaf(a5.w,b1.w,dot1);
            nx0  = fmaf(a4.x,a4.x,nx0);  nx0  = fmaf(a4.y,a4.y,nx0);
            nx0  = fmaf(a4.z,a4.z,nx0);  nx0  = fmaf(a4.w,a4.w,nx0);
            nx1  = fmaf(a5.x,a5.x,nx1);  nx1  = fmaf(a5.y,a5.y,nx1);
            nx1  = fmaf(a5.z,a5.z,nx1);  nx1  = fmaf(a5.w,a5.w,nx1);
        }
        {
            float4 b0 = __ldg(cr + 48), b1 = __ldg(cr + 56);
            dot0 = fmaf(a6.x,b0.x,dot0); dot0 = fmaf(a6.y,b0.y,dot0);
            dot0 = fmaf(a6.z,b0.z,dot0); dot0 = fmaf(a6.w,b0.w,dot0);
            dot1 = fmaf(a7.x,b1.x,dot1); dot1 = fmaf(a7.y,b1.y,dot1);
            dot1 = fmaf(a7.z,b1.z,dot1); dot1 = fmaf(a7.w,b1.w,dot1);
            nx0  = fmaf(a6.x,a6.x,nx0);  nx0  = fmaf(a6.y,a6.y,nx0);
            nx0  = fmaf(a6.z,a6.z,nx0);  nx0  = fmaf(a6.w,a6.w,nx0);
            nx1  = fmaf(a7.x,a7.x,nx1);  nx1  = fmaf(a7.y,a7.y,nx1);
            nx1  = fmaf(a7.z,a7.z,nx1);  nx1  = fmaf(a7.w,a7.w,nx1);
        }

        float dot = dot0 + dot1;
        float nx2 = nx0 + nx1;

        // Parallel 8-lane group reduction (all 4 rows simultaneously).
        dot += __shfl_xor_sync(0xFFFFFFFFu, dot, 4);
        nx2 += __shfl_xor_sync(0xFFFFFFFFu, nx2, 4);
        float w = (lane & 4) ? nx2 : dot;
        w += __shfl_xor_sync(0xFFFFFFFFu, w, 2);
        w += __shfl_xor_sync(0xFFFFFFFFu, w, 1);
        const float nxv = __shfl_xor_sync(0xFFFFFFFFu, w, 4);

        if (sub == 0) {
            float cd = 1.0f - w * rsqrtf(fmaxf(nxv, 1e-16f));
            cd = fminf(fmaxf(cd, CLAMP_MIN), CLAMP_MAX);
            acc += cd;
        }
    }

    // Tail rows (N not multiple of 4): handled by warp 0 of block 0.
    if (gwarp == 0) {
        for (int row = Nq; row < N; ++row) {
            const int lab = __ldg(&ref_label[row]);
            const float4* __restrict__ xr = reinterpret_cast<const float4*>(ref_emb) + (size_t)row * 64;
            const float4* __restrict__ cr = reinterpret_cast<const float4*>(g_cnorm) + (size_t)lab * 64;
            float4 a0 = xr[lane], a1 = xr[32 + lane];
            float4 b0 = cr[lane], b1 = cr[32 + lane];
            float dot = 0.f, nx2 = 0.f;
            dot = fmaf(a0.x,b0.x,dot); dot = fmaf(a0.y,b0.y,dot);
            dot = fmaf(a0.z,b0.z,dot); dot = fmaf(a0.w,b0.w,dot);
            dot = fmaf(a1.x,b1.x,dot); dot = fmaf(a1.y,b1.y,dot);
            dot = fmaf(a1.z,b1.z,dot); dot = fmaf(a1.w,b1.w,dot);
            nx2 = fmaf(a0.x,a0.x,nx2); nx2 = fmaf(a0.y,a0.y,nx2);
            nx2 = fmaf(a0.z,a0.z,nx2); nx2 = fmaf(a0.w,a0.w,nx2);
            nx2 = fmaf(a1.x,a1.x,nx2); nx2 = fmaf(a1.y,a1.y,nx2);
            nx2 = fmaf(a1.z,a1.z,nx2); nx2 = fmaf(a1.w,a1.w,nx2);
            #pragma unroll
            for (int off = 16; off > 0; off >>= 1) {
                dot += __shfl_xor_sync(0xFFFFFFFFu, dot, off);
                nx2 += __shfl_xor_sync(0xFFFFFFFFu, nx2, off);
            }
            if (lane == 0) {
                float cd = 1.0f - dot * rsqrtf(fmaxf(nx2, 1e-16f));
                acc += fminf(fmaxf(cd, CLAMP_MIN), CLAMP_MAX);
            }
        }
    }

    // Fold the 4 group leaders (lanes 0,8,16,24) into lane 0.
    acc += __shfl_xor_sync(0xFFFFFFFFu, acc, 8);
    acc += __shfl_xor_sync(0xFFFFFFFFu, acc, 16);

    if (lane == 0) ssum[wid] = acc;
    __syncthreads();

    if (wid == 0) {
        float v = (lane < warps_per_block) ? ssum[lane] : 0.0f;
        #pragma unroll
        for (int off = 8; off > 0; off >>= 1)
            v += __shfl_xor_sync(0xFFFFFFFFu, v, off);
        if (lane == 0)
            atomicAdd(out, v * inv_n);
    }
}

extern "C" void kernel_launch(void* const* d_in, const int* in_sizes, int n_in,
                              void* d_out, int out_size) {
    const float* ref_emb   = (const float*)d_in[0];
    const int*   ref_label = (const int*)d_in[1];
    const float* centers   = (const float*)d_in[2];
    float* out = (float*)d_out;

    const int N = in_sizes[1];
    const int C = in_sizes[2] / 256;     // D = 256
    const float inv_n = 1.0f / (float)N;

    const int prep_threads = 512;
    const int prep_blocks = (C * 32 + prep_threads - 1) / prep_threads;
    prep_kernel<<<prep_blocks, prep_threads>>>(centers, out, C);

    const int threads = 512;             // 16 warps/block
    const int blocks  = 148 * 2;         // 2 blocks/SM -> 32 warps/SM, regs <= 64
    inner_cos_kernel<<<blocks, threads>>>(ref_emb, ref_label, out, N, inv_n);
}

// round 6
// speedup vs baseline: 1.1791x; 1.1791x over previous
#include <cuda_runtime.h>
#include <cuda_bf16.h>

#define CLAMP_MIN 1e-12f
#define CLAMP_MAX 1e12f

// Pre-normalized centers scratch (C <= 256, D = 256)
__device__ float g_cnorm[256 * 256];

// Prep: zero the output and write normalized centers (one warp per center row).
__global__ void prep_kernel(const float* __restrict__ centers, float* __restrict__ out, int C) {
    if (blockIdx.x == 0 && threadIdx.x == 0) out[0] = 0.0f;

    const int warp = (blockIdx.x * blockDim.x + threadIdx.x) >> 5;
    const int lane = threadIdx.x & 31;
    if (warp >= C) return;

    const float4* __restrict__ cr = reinterpret_cast<const float4*>(centers) + (size_t)warp * 64;
    float4 b0 = cr[lane];
    float4 b1 = cr[32 + lane];

    float s = 0.0f;
    s = fmaf(b0.x, b0.x, s); s = fmaf(b0.y, b0.y, s);
    s = fmaf(b0.z, b0.z, s); s = fmaf(b0.w, b0.w, s);
    s = fmaf(b1.x, b1.x, s); s = fmaf(b1.y, b1.y, s);
    s = fmaf(b1.z, b1.z, s); s = fmaf(b1.w, b1.w, s);

    #pragma unroll
    for (int off = 16; off > 0; off >>= 1)
        s += __shfl_xor_sync(0xFFFFFFFFu, s, off);

    const float inv = rsqrtf(fmaxf(s, 1e-24f));
    b0.x *= inv; b0.y *= inv; b0.z *= inv; b0.w *= inv;
    b1.x *= inv; b1.y *= inv; b1.z *= inv; b1.w *= inv;

    float4* __restrict__ dst = reinterpret_cast<float4*>(g_cnorm) + (size_t)warp * 64;
    dst[lane]      = b0;
    dst[32 + lane] = b1;
}

// Main: persistent grid, warp-per-row, software-pipelined:
// next iteration's label + emb tile prefetched while current row computes.
// 512 thr x 3 blocks/SM (48 warps/SM), regs capped at 42.
__global__ __launch_bounds__(512, 3)
void inner_cos_kernel(const float* __restrict__ ref_emb,
                      const int*   __restrict__ ref_label,
                      float* __restrict__ out,
                      int N, float inv_n) {
    const int lane = threadIdx.x & 31;
    const int wid  = threadIdx.x >> 5;
    const int warps_per_block = blockDim.x >> 5;
    const int gwarp = blockIdx.x * warps_per_block + wid;
    const int total_warps = gridDim.x * warps_per_block;

    __shared__ float ssum[16];

    const float4* __restrict__ emb4 = reinterpret_cast<const float4*>(ref_emb);

    float acc = 0.0f;   // meaningful on lane 0

    int row = gwarp;
    if (row < N) {
        // Prologue: current row's label + emb tile.
        int lab = __ldg(&ref_label[row]);
        float4 a0 = __ldcs(&emb4[(size_t)row * 64 + lane]);
        float4 a1 = __ldcs(&emb4[(size_t)row * 64 + 32 + lane]);

        while (true) {
            const int nrow = row + total_warps;
            const bool has_next = (nrow < N);

            // Prefetch next iteration (independent of current results).
            int nlab = 0;
            float4 na0, na1;
            if (has_next) {
                nlab = __ldg(&ref_label[nrow]);
                na0  = __ldcs(&emb4[(size_t)nrow * 64 + lane]);
                na1  = __ldcs(&emb4[(size_t)nrow * 64 + 32 + lane]);
            }

            // Current centers (lab landed an iteration ago; L1-resident data).
            const float4* __restrict__ cr = reinterpret_cast<const float4*>(g_cnorm) + (size_t)lab * 64;
            float4 b0 = __ldg(&cr[lane]);
            float4 b1 = __ldg(&cr[32 + lane]);

            float dot = 0.0f, nx2 = 0.0f;
            dot = fmaf(a0.x, b0.x, dot); dot = fmaf(a0.y, b0.y, dot);
            dot = fmaf(a0.z, b0.z, dot); dot = fmaf(a0.w, b0.w, dot);
            dot = fmaf(a1.x, b1.x, dot); dot = fmaf(a1.y, b1.y, dot);
            dot = fmaf(a1.z, b1.z, dot); dot = fmaf(a1.w, b1.w, dot);
            nx2 = fmaf(a0.x, a0.x, nx2); nx2 = fmaf(a0.y, a0.y, nx2);
            nx2 = fmaf(a0.z, a0.z, nx2); nx2 = fmaf(a0.w, a0.w, nx2);
            nx2 = fmaf(a1.x, a1.x, nx2); nx2 = fmaf(a1.y, a1.y, nx2);
            nx2 = fmaf(a1.z, a1.z, nx2); nx2 = fmaf(a1.w, a1.w, nx2);

            // Split reduction: xor16 both, half-warps finish one value each.
            dot += __shfl_xor_sync(0xFFFFFFFFu, dot, 16);
            nx2 += __shfl_xor_sync(0xFFFFFFFFu, nx2, 16);
            float w = (lane < 16) ? dot : nx2;
            w += __shfl_xor_sync(0xFFFFFFFFu, w, 8);
            w += __shfl_xor_sync(0xFFFFFFFFu, w, 4);
            w += __shfl_xor_sync(0xFFFFFFFFu, w, 2);
            w += __shfl_xor_sync(0xFFFFFFFFu, w, 1);
            const float nxv = __shfl_xor_sync(0xFFFFFFFFu, w, 16);

            if (lane == 0) {
                float cd = 1.0f - w * rsqrtf(fmaxf(nxv, 1e-16f));
                cd = fminf(fmaxf(cd, CLAMP_MIN), CLAMP_MAX);
                acc += cd;
            }

            if (!has_next) break;
            row = nrow; lab = nlab; a0 = na0; a1 = na1;
        }
    }

    if (lane == 0) ssum[wid] = acc;
    __syncthreads();

    if (wid == 0) {
        float v = (lane < warps_per_block) ? ssum[lane] : 0.0f;
        #pragma unroll
        for (int off = 8; off > 0; off >>= 1)
            v += __shfl_xor_sync(0xFFFFFFFFu, v, off);
        if (lane == 0)
            atomicAdd(out, v * inv_n);
    }
}

extern "C" void kernel_launch(void* const* d_in, const int* in_sizes, int n_in,
                              void* d_out, int out_size) {
    const float* ref_emb   = (const float*)d_in[0];
    const int*   ref_label = (const int*)d_in[1];
    const float* centers   = (const float*)d_in[2];
    float* out = (float*)d_out;

    const int N = in_sizes[1];
    const int C = in_sizes[2] / 256;     // D = 256
    const float inv_n = 1.0f / (float)N;

    const int prep_threads = 512;
    const int prep_blocks = (C * 32 + prep_threads - 1) / prep_threads;
    prep_kernel<<<prep_blocks, prep_threads>>>(centers, out, C);

    const int threads = 512;             // 16 warps/block
    const int blocks  = 148 * 3;         // 3 blocks/SM -> 48 warps/SM
    inner_cos_kernel<<<blocks, threads>>>(ref_emb, ref_label, out, N, inv_n);
}